// round 1
// baseline (speedup 1.0000x reference)
#include <cuda_runtime.h>
#include <cstdint>

#define NROWS   131072
#define DIM     64
#define NE      1024
#define DECAYF  0.99f
#define ONE_M_D 0.01f
#define EPSF    1e-5f

// output layout (float32), tuple order of reference
#define NQ       8388608
#define OFF_Q    0
#define OFF_DIFF 8388608
#define OFF_IND  8388609
#define OFF_NCS  8519681
#define OFF_NEA  8520705
#define OFF_NE   8586241

// device scratch (no allocations allowed)
__device__ float  g_en[NE];          // ||e_j||^2
__device__ float  g_count[NE];       // onehot histogram
__device__ float  g_esum[NE * DIM];  // segment sum, [j][k] (transposed for contiguous atomics)
__device__ double g_diff;            // sum of (q-x)^2

// ---------- packed f32x2 helpers ----------
__device__ __forceinline__ unsigned long long pack2(float lo, float hi) {
    unsigned long long r;
    asm("mov.b64 %0, {%1, %2};" : "=l"(r) : "f"(lo), "f"(hi));
    return r;
}
__device__ __forceinline__ void unpack2(unsigned long long v, float& lo, float& hi) {
    asm("mov.b64 {%0, %1}, %2;" : "=f"(lo), "=f"(hi) : "l"(v));
}
__device__ __forceinline__ unsigned long long fma2(unsigned long long a,
                                                   unsigned long long b,
                                                   unsigned long long c) {
    unsigned long long d;
    asm("fma.rn.f32x2 %0, %1, %2, %3;" : "=l"(d) : "l"(a), "l"(b), "l"(c));
    return d;
}

// ---------- K0: zero scratch + compute ||e_j||^2 ----------
__global__ void k0_init(const float* __restrict__ embed) {
    int gid = blockIdx.x * blockDim.x + threadIdx.x;   // 65536 threads
    if (gid < NE * DIM) g_esum[gid] = 0.0f;
    if (gid < NE) {
        g_count[gid] = 0.0f;
        float s = 0.0f;
        #pragma unroll
        for (int k = 0; k < DIM; k++) {
            float e = embed[k * NE + gid];
            s = fmaf(e, e, s);
        }
        g_en[gid] = s;
    }
    if (gid == 0) g_diff = 0.0;
}

// ---------- K1: fused GEMM + argmin + gather + stats ----------
#define BM 128
#define BN 128
static const int SXT_F  = 64 * 132;   // x^T tile, padded stride 132
static const int SBUF_F = 8320;       // stage / E-chunk / Q tile (union)
static const int SVAL_F = 128 * 16;   // per-row candidate values
static const int SMEM_FLOATS = SXT_F + SBUF_F + SVAL_F + SVAL_F;
static const int SMEM_BYTES  = SMEM_FLOATS * 4;   // 83456 B

__global__ void __launch_bounds__(256, 2) k1_main(
    const float* __restrict__ x,
    const float* __restrict__ embed,
    float* __restrict__ out)
{
    extern __shared__ float sm[];
    float* sXT  = sm;                 // [64][132]  x transposed
    float* sBuf = sm + SXT_F;         // staging / E chunk / Q tile
    float* sVal = sBuf + SBUF_F;      // [128][16]
    int*   sIdx = (int*)(sVal + SVAL_F);

    const int tid = threadIdx.x;
    const int ty  = tid >> 4;         // 0..15 -> rows ty*8..ty*8+7
    const int tx  = tid & 15;         // 0..15 -> 8 cols per chunk
    const int rowBase = blockIdx.x * BM;

    // Phase A: coalesced x -> stage [128][65]
    {
        const float* xg = x + (size_t)rowBase * DIM;
        #pragma unroll
        for (int it = 0; it < 32; ++it) {
            int lin = tid + it * 256;
            int r = lin >> 6, k = lin & 63;
            sBuf[r * 65 + k] = xg[lin];
        }
    }
    __syncthreads();
    // Phase B: transpose -> sXT[k][r], conflict-free both sides
    #pragma unroll
    for (int it = 0; it < 32; ++it) {
        int lin = tid + it * 256;
        int k = lin >> 7, r = lin & 127;
        sXT[k * 132 + r] = sBuf[r * 65 + k];
    }
    __syncthreads();

    float best[8];
    int   bidx[8];
    #pragma unroll
    for (int i = 0; i < 8; i++) { best[i] = -3.4e38f; bidx[i] = 0; }

    for (int ch = 0; ch < 8; ++ch) {
        const int cb = ch * BN;
        // load E chunk [64][128] coalesced
        {
            const float* eg = embed + cb;
            #pragma unroll
            for (int it = 0; it < 32; ++it) {
                int lin = tid + it * 256;
                int k = lin >> 7, c = lin & 127;
                sBuf[k * BN + c] = eg[k * NE + c];
            }
        }
        __syncthreads();

        // acc_j initialized to -0.5*||e_j||^2; accumulate f.e
        unsigned long long acc[8][4];
        {
            const float4* en4 = (const float4*)(g_en + cb + tx * 8);
            float4 ea = en4[0], eb = en4[1];
            unsigned long long i0 = pack2(-0.5f * ea.x, -0.5f * ea.y);
            unsigned long long i1 = pack2(-0.5f * ea.z, -0.5f * ea.w);
            unsigned long long i2 = pack2(-0.5f * eb.x, -0.5f * eb.y);
            unsigned long long i3 = pack2(-0.5f * eb.z, -0.5f * eb.w);
            #pragma unroll
            for (int i = 0; i < 8; i++) {
                acc[i][0] = i0; acc[i][1] = i1; acc[i][2] = i2; acc[i][3] = i3;
            }
        }

        #pragma unroll 8
        for (int k = 0; k < 64; k++) {
            const float4* xp = (const float4*)(sXT + k * 132 + ty * 8);
            float4 xa = xp[0], xb = xp[1];
            const ulonglong2* ep = (const ulonglong2*)(sBuf + k * BN + tx * 8);
            ulonglong2 e01 = ep[0], e23 = ep[1];
            unsigned long long e0 = e01.x, e1 = e01.y, e2 = e23.x, e3 = e23.y;
            float xv[8] = {xa.x, xa.y, xa.z, xa.w, xb.x, xb.y, xb.z, xb.w};
            #pragma unroll
            for (int i = 0; i < 8; i++) {
                unsigned long long xd = pack2(xv[i], xv[i]);
                acc[i][0] = fma2(xd, e0, acc[i][0]);
                acc[i][1] = fma2(xd, e1, acc[i][1]);
                acc[i][2] = fma2(xd, e2, acc[i][2]);
                acc[i][3] = fma2(xd, e3, acc[i][3]);
            }
        }

        // running argmax (== argmin of dist)
        #pragma unroll
        for (int i = 0; i < 8; i++) {
            #pragma unroll
            for (int p = 0; p < 4; p++) {
                float lo, hi;
                unpack2(acc[i][p], lo, hi);
                int j = cb + tx * 8 + 2 * p;
                if (lo > best[i]) { best[i] = lo; bidx[i] = j; }
                if (hi > best[i]) { best[i] = hi; bidx[i] = j + 1; }
            }
        }
        __syncthreads();
    }

    // per-row reduction across the 16 column-threads
    #pragma unroll
    for (int i = 0; i < 8; i++) {
        int r = ty * 8 + i;
        sVal[r * 16 + tx] = best[i];
        sIdx[r * 16 + tx] = bidx[i];
    }
    __syncthreads();

    float dsum = 0.0f;
    if (tid < BM) {
        int r = tid;
        float bv = sVal[r * 16];
        int   bj = sIdx[r * 16];
        #pragma unroll
        for (int t2 = 1; t2 < 16; t2++) {
            float v = sVal[r * 16 + t2];
            int   j = sIdx[r * 16 + t2];
            if (v > bv || (v == bv && j < bj)) { bv = v; bj = j; }
        }
        out[OFF_IND + rowBase + r] = (float)bj;
        atomicAdd(&g_count[bj], 1.0f);

        // gather codeword, diff partial, segment-sum atomics, stage Q tile
        const float* ecol = embed + bj;
        #pragma unroll 8
        for (int k = 0; k < 64; k++) {
            float q  = ecol[k * NE];
            float xv = sXT[k * 132 + r];
            float d  = q - xv;
            dsum = fmaf(d, d, dsum);
            sBuf[r * 64 + k] = q;
            atomicAdd(&g_esum[bj * 64 + k], xv);
        }
    }
    #pragma unroll
    for (int o = 16; o; o >>= 1) dsum += __shfl_xor_sync(0xffffffffu, dsum, o);
    if ((tid & 31) == 0 && tid < BM) atomicAdd(&g_diff, (double)dsum);
    __syncthreads();

    // coalesced Q tile -> out
    float4* og = (float4*)(out + (size_t)rowBase * DIM);
    const float4* sq4 = (const float4*)sBuf;
    #pragma unroll
    for (int it = 0; it < 8; ++it) og[tid + it * 256] = sq4[tid + it * 256];
}

// ---------- K2: EMA updates + finalize diff ----------
__global__ void k2_finish(const float* __restrict__ cluster_size,
                          const float* __restrict__ embed_avg,
                          float* __restrict__ out)
{
    __shared__ double ssum[32];
    __shared__ float  s_n;
    int j = threadIdx.x;   // 1024 threads

    float ncs = DECAYF * cluster_size[j] + ONE_M_D * g_count[j];
    out[OFF_NCS + j] = ncs;

    double v = (double)ncs;
    #pragma unroll
    for (int o = 16; o; o >>= 1) v += __shfl_xor_sync(0xffffffffu, v, o);
    if ((j & 31) == 0) ssum[j >> 5] = v;
    __syncthreads();
    if (j < 32) {
        double t = ssum[j];
        #pragma unroll
        for (int o = 16; o; o >>= 1) t += __shfl_xor_sync(0xffffffffu, t, o);
        if (j == 0) s_n = (float)t;
    }
    __syncthreads();
    float n  = s_n;
    float cs = (ncs + EPSF) / (n + (float)NE * EPSF) * n;

    #pragma unroll
    for (int k = 0; k < 64; k++) {
        float ea = DECAYF * embed_avg[k * NE + j] + ONE_M_D * g_esum[j * 64 + k];
        out[OFF_NEA + k * NE + j] = ea;
        out[OFF_NE  + k * NE + j] = ea / cs;
    }
    if (j == 0) out[OFF_DIFF] = (float)(g_diff * (1.0 / 8388608.0));
}

// ---------- launch ----------
extern "C" void kernel_launch(void* const* d_in, const int* in_sizes, int n_in,
                              void* d_out, int out_size) {
    const float* x            = (const float*)d_in[0];
    const float* embed        = (const float*)d_in[1];
    const float* cluster_size = (const float*)d_in[2];
    const float* embed_avg    = (const float*)d_in[3];
    float* out = (float*)d_out;

    cudaFuncSetAttribute(k1_main, cudaFuncAttributeMaxDynamicSharedMemorySize, SMEM_BYTES);

    k0_init<<<256, 256>>>(embed);
    k1_main<<<NROWS / BM, 256, SMEM_BYTES>>>(x, embed, out);
    k2_finish<<<1, 1024>>>(cluster_size, embed_avg, out);
}